// round 6
// baseline (speedup 1.0000x reference)
#include <cuda_runtime.h>
#include <cuda_bf16.h>

#define W_IN  1024
#define H_IN  1024
#define W_OUT 512
#define H_OUT 512
#define NBLOCKS 1184   // 148 SMs * 8 resident CTAs (256 thr, 32 regs -> occ 8)

// Haar DWT level 1, zero left/top pad, stride 2.
// out(h',w') <- x rows {2h'-1, 2h'}, cols {2w'-1, 2w'}.
//
// Persistent CTAs: each of NBLOCKS CTAs owns a CONTIGUOUS slab of row-pair
// tasks (task = 2 output rows of one (b,c) plane), so each SM streams
// sequentially through its input slab (DRAM page locality) and keeps steady
// write cursors in the 4 subband planes.
//
// Within a task: 256 threads = 2 output rows; thread i (0..127 in its row)
// owns output cols 4i..4i+3 <- input cols 8i-1..8i+6 of rows 2h-1, 2h.
// 4 LDG.128 + carry shfl, 4 STG.128 (one per subband). Fully coalesced.
__global__ void __launch_bounds__(256) dwt_haar_kernel(
    const float* __restrict__ x, float* __restrict__ out, int n_bc)
{
    const int i    = threadIdx.x & 127;
    const int lane = threadIdx.x & 31;
    const int hofs = threadIdx.x >> 7;           // 0 or 1: which row of the pair
    const int cb   = i << 3;                     // input col base = 8i
    const float a  = 0.7071067811865476f;

    const int total = n_bc * (H_OUT / 2);        // row-pair tasks (48*256 = 12288)
    const int start = (int)(((long long)blockIdx.x * total) / NBLOCKS);
    const int end   = (int)(((long long)(blockIdx.x + 1) * total) / NBLOCKS);

    const size_t P = (size_t)n_bc * H_OUT * W_OUT;   // subband plane stride

    for (int t = start; t < end; ++t) {
        const int bc = t >> 8;                   // t / 256
        const int h  = ((t & 255) << 1) + hofs;  // output row

        const float* rowb = x + ((size_t)bc * H_IN + (size_t)(2 * h)) * W_IN;

        float4 vb0 = __ldcs(reinterpret_cast<const float4*>(rowb + cb));
        float4 vb1 = __ldcs(reinterpret_cast<const float4*>(rowb + cb + 4));
        float4 vt0, vt1;
        if (h > 0) {
            const float* rowt = rowb - W_IN;     // input row 2h-1
            vt0 = __ldcs(reinterpret_cast<const float4*>(rowt + cb));
            vt1 = __ldcs(reinterpret_cast<const float4*>(rowt + cb + 4));
        } else {
            vt0 = make_float4(0.f, 0.f, 0.f, 0.f);
            vt1 = make_float4(0.f, 0.f, 0.f, 0.f);
        }

        // carry = input col 8i-1 (previous lane's vt1.w / vb1.w)
        float tm1 = __shfl_up_sync(0xffffffffu, vt1.w, 1);
        float bm1 = __shfl_up_sync(0xffffffffu, vb1.w, 1);
        if (lane == 0) {
            tm1 = 0.0f; bm1 = 0.0f;
            if (cb != 0) {
                bm1 = __ldg(rowb + cb - 1);
                if (h > 0) tm1 = __ldg(rowb - W_IN + cb - 1);
            }
        }

        // 4 output cols; pairs: (8i-1,8i) (8i+1,8i+2) (8i+3,8i+4) (8i+5,8i+6)
        float tl[4] = { tm1,   vt0.y, vt0.w, vt1.y };
        float tr[4] = { vt0.x, vt0.z, vt1.x, vt1.z };
        float bl[4] = { bm1,   vb0.y, vb0.w, vb1.y };
        float br[4] = { vb0.x, vb0.z, vb1.x, vb1.z };

        float ll[4], lh[4], hl[4], hh[4];
        #pragma unroll
        for (int j = 0; j < 4; ++j) {
            float h0t = a * (tl[j] + tr[j]), h1t = a * (tr[j] - tl[j]);
            float h0b = a * (bl[j] + br[j]), h1b = a * (br[j] - bl[j]);
            ll[j] = a * (h0t + h0b);
            lh[j] = a * (h0b - h0t);
            hl[j] = a * (h1t + h1b);
            hh[j] = a * (h1b - h1t);
        }

        float* o = out + ((size_t)bc * H_OUT + h) * W_OUT + (i << 2);
        __stcs(reinterpret_cast<float4*>(o + 0 * P), make_float4(ll[0], ll[1], ll[2], ll[3]));
        __stcs(reinterpret_cast<float4*>(o + 1 * P), make_float4(lh[0], lh[1], lh[2], lh[3]));
        __stcs(reinterpret_cast<float4*>(o + 2 * P), make_float4(hl[0], hl[1], hl[2], hl[3]));
        __stcs(reinterpret_cast<float4*>(o + 3 * P), make_float4(hh[0], hh[1], hh[2], hh[3]));
    }
}

extern "C" void kernel_launch(void* const* d_in, const int* in_sizes, int n_in,
                              void* d_out, int out_size)
{
    const float* x = (const float*)d_in[0];   // (16,3,1024,1024) fp32
    float* out = (float*)d_out;               // [LL,LH,HL,HH] each (16,3,512,512)

    const int n_bc = in_sizes[0] / (H_IN * W_IN);   // 48

    dwt_haar_kernel<<<NBLOCKS, 256>>>(x, out, n_bc);
}

// round 7
// speedup vs baseline: 1.0967x; 1.0967x over previous
#include <cuda_runtime.h>
#include <cuda_bf16.h>

#define W_IN  1024
#define H_IN  1024
#define W_OUT 512
#define H_OUT 512

// Haar DWT level 1, zero left/top pad, stride 2.
// out(h',w') <- x rows {2h'-1, 2h'}, cols {2w'-1, 2w'}.
//
// Block = 256 threads = 2 output rows (one row-pair) of one (b,c) plane.
// Thread i (0..127 within its row) owns output cols 4i..4i+3, i.e. input
// cols 8i-1..8i+6 of rows 2h-1, 2h: 4 front-batched LDG.128 (512B/warp),
// carry col 8i-1 via shfl (lane 0: scalar LDG), 4 STG.128 (one per subband).
// Grid axes ordered so consecutive block ids vary the PLANE index fastest:
// the chip-resident CTA set spans all 48 planes at once (max DRAM bank
// parallelism) instead of one contiguous window.
__global__ void __launch_bounds__(256) dwt_haar_kernel(
    const float* __restrict__ x, float* __restrict__ out, int n_bc)
{
    const int i    = threadIdx.x & 127;          // position within the row
    const int lane = threadIdx.x & 31;
    const int h    = (blockIdx.z << 1) + (threadIdx.x >> 7);   // output row
    const int bc   = blockIdx.y;                 // plane index (fastest axis)
    const int cb   = i << 3;                     // input col base = 8i
    const float a  = 0.7071067811865476f;

    const float* rowb = x + ((size_t)bc * H_IN + (size_t)(2 * h)) * W_IN;

    float4 vb0 = __ldcs(reinterpret_cast<const float4*>(rowb + cb));
    float4 vb1 = __ldcs(reinterpret_cast<const float4*>(rowb + cb + 4));
    float4 vt0, vt1;
    if (h > 0) {
        const float* rowt = rowb - W_IN;         // input row 2h-1
        vt0 = __ldcs(reinterpret_cast<const float4*>(rowt + cb));
        vt1 = __ldcs(reinterpret_cast<const float4*>(rowt + cb + 4));
    } else {
        vt0 = make_float4(0.f, 0.f, 0.f, 0.f);
        vt1 = make_float4(0.f, 0.f, 0.f, 0.f);
    }

    // carry = input col 8i-1 (the previous lane's vt1.w / vb1.w)
    float tm1 = __shfl_up_sync(0xffffffffu, vt1.w, 1);
    float bm1 = __shfl_up_sync(0xffffffffu, vb1.w, 1);
    if (lane == 0) {
        tm1 = 0.0f; bm1 = 0.0f;
        if (cb != 0) {
            bm1 = __ldg(rowb + cb - 1);
            if (h > 0) tm1 = __ldg(rowb - W_IN + cb - 1);
        }
    }

    // 4 output cols; input pairs: (8i-1,8i) (8i+1,8i+2) (8i+3,8i+4) (8i+5,8i+6)
    float tl[4] = { tm1,   vt0.y, vt0.w, vt1.y };
    float tr[4] = { vt0.x, vt0.z, vt1.x, vt1.z };
    float bl[4] = { bm1,   vb0.y, vb0.w, vb1.y };
    float br[4] = { vb0.x, vb0.z, vb1.x, vb1.z };

    float ll[4], lh[4], hl[4], hh[4];
    #pragma unroll
    for (int j = 0; j < 4; ++j) {
        float h0t = a * (tl[j] + tr[j]), h1t = a * (tr[j] - tl[j]);
        float h0b = a * (bl[j] + br[j]), h1b = a * (br[j] - bl[j]);
        ll[j] = a * (h0t + h0b);
        lh[j] = a * (h0b - h0t);
        hl[j] = a * (h1t + h1b);
        hh[j] = a * (h1b - h1t);
    }

    const size_t P = (size_t)n_bc * H_OUT * W_OUT;     // subband plane stride
    float* o = out + ((size_t)bc * H_OUT + h) * W_OUT + (i << 2);

    __stcs(reinterpret_cast<float4*>(o + 0 * P), make_float4(ll[0], ll[1], ll[2], ll[3]));
    __stcs(reinterpret_cast<float4*>(o + 1 * P), make_float4(lh[0], lh[1], lh[2], lh[3]));
    __stcs(reinterpret_cast<float4*>(o + 2 * P), make_float4(hl[0], hl[1], hl[2], hl[3]));
    __stcs(reinterpret_cast<float4*>(o + 3 * P), make_float4(hh[0], hh[1], hh[2], hh[3]));
}

extern "C" void kernel_launch(void* const* d_in, const int* in_sizes, int n_in,
                              void* d_out, int out_size)
{
    const float* x = (const float*)d_in[0];   // (16,3,1024,1024) fp32
    float* out = (float*)d_out;               // [LL,LH,HL,HH] each (16,3,512,512)

    const int n_bc = in_sizes[0] / (H_IN * W_IN);   // 48

    dim3 block(256, 1, 1);
    dim3 grid(1, n_bc, H_OUT / 2);            // plane index varies fastest
    dwt_haar_kernel<<<grid, block>>>(x, out, n_bc);
}